// round 9
// baseline (speedup 1.0000x reference)
#include <cuda_runtime.h>
#include <math.h>

// ReacPartialGbModel: B=4096 RK4 integrations, T=256 steps.
// r2-> cubic-Hermite LUT B(x1); r1 -> single LUT R(x0) with A(x0) recovered
// algebraically: A = 0.1*x0 + 1/6 + (2/3)*R. LUTs live in shared memory.
// TWO elements per warp: element B's r3-block overlaps element A's k-chain
// (the two are strictly serial within one element). History rings in smem
// (uniform broadcast reads, lane-0 writes). r3 software-pipelined as before.

namespace {

constexpr int kT = 256;
constexpr int kB = 4096;
constexpr int kN2 = 1024;              // LUT intervals over [-16,16)
constexpr float kH2    = 1.0f / 32.0f;
constexpr float kInvH2 = 32.0f;
constexpr float kSc    = 2.885390081777927f;  // 2*log2(e)

__device__ __align__(16) float4 g_lutR[kN2];
__device__ __align__(16) float4 g_lutB[kN2];

typedef unsigned long long ull;

// ---------------- helpers ---------------------------------------------------
__device__ __forceinline__ float tanh_acc(float x) {
    float ax = fabsf(x);
    float e  = __expf(-2.0f * ax);
    float r  = __fdividef(1.0f - e, 1.0f + e);
    return copysignf(r, x);
}
__device__ __forceinline__ float tanh_pre(float a) {   // input prescaled 2*log2e
    float e; asm("ex2.approx.f32 %0, %1;" : "=f"(e) : "f"(a));
    float s = e + 1.0f;
    float r; asm("rcp.approx.f32 %0, %1;" : "=f"(r) : "f"(s));
    return fmaf(-2.0f, r, 1.0f);
}
__device__ __forceinline__ ull fma2(ull a, ull b, ull c) {
    ull d; asm("fma.rn.f32x2 %0, %1, %2, %3;" : "=l"(d) : "l"(a), "l"(b), "l"(c));
    return d;
}
__device__ __forceinline__ ull add2(ull a, ull b) {
    ull d; asm("add.rn.f32x2 %0, %1, %2;" : "=l"(d) : "l"(a), "l"(b));
    return d;
}
__device__ __forceinline__ ull pk(float lo, float hi) {
    ull d; asm("mov.b64 %0, {%1, %2};" : "=l"(d) : "f"(lo), "f"(hi));
    return d;
}
__device__ __forceinline__ float upadd(ull v) {
    float lo, hi; asm("mov.b64 {%0, %1}, %2;" : "=f"(lo), "=f"(hi) : "l"(v));
    return lo + hi;
}
__device__ __forceinline__ float bfly(float v) {
#pragma unroll
    for (int m = 16; m > 0; m >>= 1) v += __shfl_xor_sync(0xffffffffu, v, m);
    return v;
}

// ---------------- build kernel ----------------------------------------------
__device__ void eval_raw(float x,
                         const float* __restrict__ w0, const float* __restrict__ b0,
                         const float* __restrict__ w1, const float* __restrict__ b1,
                         const float* __restrict__ w2, const float* __restrict__ b2,
                         float& y_out, float& d_out)
{
    float t0[32], s0[32];
#pragma unroll
    for (int i = 0; i < 32; ++i) {
        float a  = fmaf(w0[i], x, b0[i]);
        float th = tanh_acc(a);
        t0[i] = th;
        s0[i] = (1.0f - th * th) * w0[i];
    }
    float y = b2[0], d = 0.0f;
    for (int j = 0; j < 32; ++j) {
        float a = b1[j], da = 0.0f;
#pragma unroll
        for (int i = 0; i < 32; ++i) {
            float w = w1[i * 32 + j];
            a  = fmaf(t0[i], w, a);
            da = fmaf(s0[i], w, da);
        }
        float th = tanh_acc(a);
        y = fmaf(w2[j], th, y);
        d = fmaf(w2[j] * (1.0f - th * th), da, d);
    }
    y_out = y; d_out = d;
}

__device__ __forceinline__ float4 hermite2(float y0, float d0, float y1, float d1) {
    float hd0 = kH2 * d0, hd1 = kH2 * d1;
    float dy  = y1 - y0;
    return make_float4(y0, hd0,
                       3.0f * dy - 2.0f * hd0 - hd1,
                       -2.0f * dy + hd0 + hd1);
}

__global__ void build_all(const float* __restrict__ W0, const float* __restrict__ B0,
                          const float* __restrict__ W1, const float* __restrict__ B1,
                          const float* __restrict__ W2, const float* __restrict__ B2,
                          const float* __restrict__ V0, const float* __restrict__ C0,
                          const float* __restrict__ V1, const float* __restrict__ C1,
                          const float* __restrict__ V2, const float* __restrict__ C2)
{
    int idx = blockIdx.x * blockDim.x + threadIdx.x;
    if (idx >= 2 * kN2) return;
    int net = idx / kN2;
    int i   = idx - net * kN2;
    float xa = -16.0f + i * kH2;
    float xb = xa + kH2;
    float y0, d0, y1, d1;
    if (net == 0) {
        eval_raw(xa, W0, B0, W1, B1, W2, B2, y0, d0);
        eval_raw(xb, W0, B0, W1, B1, W2, B2, y1, d1);
        // R = r1/0.2 = 1.5*y (r1 = 0.3*y)
        g_lutR[i] = hermite2(1.5f * y0, 1.5f * d0, 1.5f * y1, 1.5f * d1);
    } else {
        eval_raw(xa, V0, C0, V1, C1, V2, C2, y0, d0);
        eval_raw(xb, V0, C0, V1, C1, V2, C2, y1, d1);
        // B = (0.1*Cb + 3*r2)*5, Cb = 0.2x+0.5, r2 = 0.2*y
        float Bv0 = (0.1f * fmaf(0.2f, xa, 0.5f) + 0.6f * y0) * 5.0f;
        float Bv1 = (0.1f * fmaf(0.2f, xb, 0.5f) + 0.6f * y1) * 5.0f;
        float Bd0 = (0.02f + 0.6f * d0) * 5.0f;
        float Bd1 = (0.02f + 0.6f * d1) * 5.0f;
        g_lutB[i] = hermite2(Bv0, Bd0, Bv1, Bd1);
    }
}

// ---------------- main kernel ------------------------------------------------
// smem floats: [rings 4x64][bufs 4x384][lutR 1024 f4][lutB 1024 f4]
constexpr int kRingFloats = 4 * 64;
constexpr int kBufFloats  = 4 * 384;
constexpr int kSmemBytes  = (kRingFloats + kBufFloats) * 4 + 2 * kN2 * 16;  // 39936

__global__ void __launch_bounds__(128, 3)
rk4_kernel(const float* __restrict__ useq, const float* __restrict__ xz0,
           const float* __restrict__ r3W0, const float* __restrict__ r3b0,
           const float* __restrict__ r3W1, const float* __restrict__ r3b1,
           const float* __restrict__ r3W2, const float* __restrict__ r3b2,
           float* __restrict__ out)
{
    extern __shared__ __align__(16) float smemraw[];
    const int wslot = threadIdx.x >> 5;
    const int lane  = threadIdx.x & 31;
    const int wid   = blockIdx.x * 4 + wslot;   // warp id, 2 elements each

    float* ring = smemraw + wslot * 64;
    ull*   xqA  = reinterpret_cast<ull*>(ring);          // 8 ull
    float* upA  = ring + 16;                              // 8 f
    ull*   xqB  = reinterpret_cast<ull*>(ring + 24);      // 8 ull
    float* upB  = ring + 40;                              // 8 f
    float* bufA = smemraw + kRingFloats + wslot * 384;    // 2x96 parity
    float* bufB = bufA + 192;
    float4* sR = reinterpret_cast<float4*>(smemraw + kRingFloats + kBufFloats);
    float4* sBt = sR + kN2;

    for (int k = threadIdx.x; k < kN2; k += 128) {
        sR[k]  = __ldg(&g_lutR[k]);
        sBt[k] = __ldg(&g_lutB[k]);
    }
    __syncthreads();

    // ---- shared p3 weights, prescaled, packed ------------------------------
    ull w30p[8], w31p[16];
    float wu[8];
#pragma unroll
    for (int j = 0; j < 8; ++j)
        w30p[j] = pk(r3W0[(2 * j) * 32 + lane] * kSc,
                     r3W0[(2 * j + 1) * 32 + lane] * kSc);
#pragma unroll
    for (int k = 0; k < 8; ++k) wu[k] = r3W0[(16 + k) * 32 + lane] * kSc;
#pragma unroll
    for (int j = 0; j < 16; ++j)
        w31p[j] = pk(r3W1[(2 * j) * 32 + lane] * kSc,
                     r3W1[(2 * j + 1) * 32 + lane] * kSc);
    const float b30s = r3b0[lane] * kSc;
    const ull   b31p = pk(r3b1[lane] * kSc, 0.0f);
    const float w32  = r3W2[lane], b32 = r3b2[0];

    auto kof = [&](float x0v, float x1v, float r3s, float cafc,
                   float& k0, float& k1v) {
        float xf0 = fmaf(x0v, kInvH2, 512.0f);
        float f0  = fminf(fmaxf(floorf(xf0), 0.0f), 1023.0f);
        float t0  = xf0 - f0;
        float4 cR = sR[(int)f0];
        float xf1 = fmaf(x1v, kInvH2, 512.0f);
        float f1  = fminf(fmaxf(floorf(xf1), 0.0f), 1023.0f);
        float t1  = xf1 - f1;
        float4 cB = sBt[(int)f1];
        float Rv = fmaf(fmaf(fmaf(cR.w, t0, cR.z), t0, cR.y), t0, cR.x);
        float Bv = fmaf(fmaf(fmaf(cB.w, t1, cB.z), t1, cB.y), t1, cB.x);
        k0  = fmaf(-2.0f / 3.0f, Rv, fmaf(-0.1f, x0v, cafc));
        k1v = (Rv - Bv) + r3s;
    };

    // ---- boot both elements -------------------------------------------------
    float Ax0, Ax1, AS1s, AUc, Ar3s1; ull AS4p;
    float Bx0, Bx1, BS1s, BUc, Br3s1; ull BS4p;
    {
        const float* xz = xz0 + (2 * wid) * 26;
        float t[26];
#pragma unroll
        for (int k = 0; k < 26; ++k) t[k] = xz[k];
        Ax0 = t[0]; Ax1 = t[1];
        ull S1 = 0ull;
#pragma unroll
        for (int j = 0; j < 8; ++j) S1 = fma2(pk(t[2+2*j], t[3+2*j]), w30p[j], S1);
        float Ua = b30s, Ub = 0.f;
#pragma unroll
        for (int k = 0; k < 8; k += 2) {
            Ua = fmaf(t[18+k],   wu[k],   Ua);
            Ub = fmaf(t[19+k],   wu[k+1], Ub);
        }
        AS1s = upadd(S1); AUc = Ua + Ub;
        ull S4 = 0ull;
#pragma unroll
        for (int j = 0; j < 7; ++j) S4 = fma2(pk(t[4+2*j], t[5+2*j]), w30p[j], S4);
        AS4p = S4;
        if (lane == 0) {
#pragma unroll
            for (int j = 0; j < 8; ++j) xqA[j] = pk(t[2+2*j], t[3+2*j]);
#pragma unroll
            for (int k = 0; k < 8; ++k) upA[k] = t[18+k];
        }
    }
    {
        const float* xz = xz0 + (2 * wid + 1) * 26;
        float t[26];
#pragma unroll
        for (int k = 0; k < 26; ++k) t[k] = xz[k];
        Bx0 = t[0]; Bx1 = t[1];
        ull S1 = 0ull;
#pragma unroll
        for (int j = 0; j < 8; ++j) S1 = fma2(pk(t[2+2*j], t[3+2*j]), w30p[j], S1);
        float Ua = b30s, Ub = 0.f;
#pragma unroll
        for (int k = 0; k < 8; k += 2) {
            Ua = fmaf(t[18+k],   wu[k],   Ua);
            Ub = fmaf(t[19+k],   wu[k+1], Ub);
        }
        BS1s = upadd(S1); BUc = Ua + Ub;
        ull S4 = 0ull;
#pragma unroll
        for (int j = 0; j < 7; ++j) S4 = fma2(pk(t[4+2*j], t[5+2*j]), w30p[j], S4);
        BS4p = S4;
        if (lane == 0) {
#pragma unroll
            for (int j = 0; j < 8; ++j) xqB[j] = pk(t[2+2*j], t[3+2*j]);
#pragma unroll
            for (int k = 0; k < 8; ++k) upB[k] = t[18+k];
        }
    }
    // boot r3s1 (k1-stage r3 of step 0) for both elements
    bufA[lane] = tanh_pre(AS1s + AUc);
    bufB[lane] = tanh_pre(BS1s + BUc);
    __syncwarp();
    {
        ull CA = b31p, CB = b31p;
        const ulonglong2* qa = reinterpret_cast<const ulonglong2*>(bufA);
        const ulonglong2* qb = reinterpret_cast<const ulonglong2*>(bufB);
#pragma unroll
        for (int q = 0; q < 8; ++q) {
            ulonglong2 va = qa[q];
            CA = fma2(va.x, w31p[2*q], CA); CA = fma2(va.y, w31p[2*q+1], CA);
            ulonglong2 vb = qb[q];
            CB = fma2(vb.x, w31p[2*q], CB); CB = fma2(vb.y, w31p[2*q+1], CB);
        }
        Ar3s1 = bfly(tanh_pre(upadd(CA)) * w32) + b32;
        Br3s1 = bfly(tanh_pre(upadd(CB)) * w32) + b32;
    }
    __syncwarp();

    const float4* uptrA = reinterpret_cast<const float4*>(useq + (2*wid)   * kT);
    const float4* uptrB = reinterpret_cast<const float4*>(useq + (2*wid+1) * kT);
    float2* outA = reinterpret_cast<float2*>(out) + (2*wid)   * kT;
    float2* outB = reinterpret_cast<float2*>(out) + (2*wid+1) * kT;

    // ---- main loop -----------------------------------------------------------
#pragma unroll 1
    for (int tb = 0; tb < kT; tb += 8) {
        float4 a0 = __ldg(uptrA + (tb>>2)), a1 = __ldg(uptrA + (tb>>2)+1);
        float4 c0 = __ldg(uptrB + (tb>>2)), c1 = __ldg(uptrB + (tb>>2)+1);
        float uuA[8] = {a0.x,a0.y,a0.z,a0.w,a1.x,a1.y,a1.z,a1.w};
        float uuB[8] = {c0.x,c0.y,c0.z,c0.w,c1.x,c1.y,c1.z,c1.w};

#pragma unroll
        for (int p = 0; p < 8; ++p) {
            const float uA = uuA[p], uB = uuB[p];
            const ull pxA = pk(Ax0, Ax1), pxB = pk(Bx0, Bx1);
            if (lane == 0) {
                outA[tb+p] = make_float2(Ax0, Ax1);
                outB[tb+p] = make_float2(Bx0, Bx1);
                xqA[p & 7] = pxA;  upA[p & 7] = uA;   // slots not read this step
                xqB[p & 7] = pxB;  upB[p & 7] = uB;
            }
            // ---- fast a3 path (x just arrived) ------------------------------
            float S4sA = upadd(fma2(pxA, w30p[7], AS4p));
            float S4sB = upadd(fma2(pxB, w30p[7], BS4p));
            float a23A = fmaf(0.5f, AS1s + S4sA, AUc);
            float a23B = fmaf(0.5f, BS1s + S4sB, BUc);
            float a4A = S4sA + AUc, a4B = S4sB + BUc;
            float UnA, UnB;
            {
                float Ua = b30s, Ub = 0.f, Va = b30s, Vb = 0.f;
#pragma unroll
                for (int k = 0; k < 6; k += 2) {
                    Ua = fmaf(upA[(p+1+k) & 7], wu[k],   Ua);
                    Ub = fmaf(upA[(p+2+k) & 7], wu[k+1], Ub);
                    Va = fmaf(upB[(p+1+k) & 7], wu[k],   Va);
                    Vb = fmaf(upB[(p+2+k) & 7], wu[k+1], Vb);
                }
                Ua = fmaf(upA[(p+7) & 7], wu[6], Ua);
                Va = fmaf(upB[(p+7) & 7], wu[6], Va);
                Ub = fmaf(uA, wu[7], Ub);
                Vb = fmaf(uB, wu[7], Vb);
                UnA = Ua + Ub; UnB = Va + Vb;
            }
            float a1nA = S4sA + UnA, a1nB = S4sB + UnB;

            float* bA = bufA + (p & 1) * 96;
            float* bB = bufB + (p & 1) * 96;
            bA[lane]      = tanh_pre(a23A);
            bA[32 + lane] = tanh_pre(a4A);
            bA[64 + lane] = tanh_pre(a1nA);
            bB[lane]      = tanh_pre(a23B);
            bB[32 + lane] = tanh_pre(a4B);
            bB[64 + lane] = tanh_pre(a1nB);
            __syncwarp();

            // ---- matvecs, both elements (ptxas interleaves freely) ----------
            ull A2a=b31p, A2b=0ull, A3a=b31p, A3b=0ull, A1a=b31p, A1b=0ull;
            ull B2a=b31p, B2b=0ull, B3a=b31p, B3b=0ull, B1a=b31p, B1b=0ull;
            const ulonglong2* qa = reinterpret_cast<const ulonglong2*>(bA);
            const ulonglong2* qb = reinterpret_cast<const ulonglong2*>(bB);
#pragma unroll
            for (int q = 0; q < 8; ++q) {
                ulonglong2 v;
                v = qa[q];      A2a = fma2(v.x, w31p[2*q], A2a); A2b = fma2(v.y, w31p[2*q+1], A2b);
                v = qa[8+q];    A3a = fma2(v.x, w31p[2*q], A3a); A3b = fma2(v.y, w31p[2*q+1], A3b);
                v = qa[16+q];   A1a = fma2(v.x, w31p[2*q], A1a); A1b = fma2(v.y, w31p[2*q+1], A1b);
                v = qb[q];      B2a = fma2(v.x, w31p[2*q], B2a); B2b = fma2(v.y, w31p[2*q+1], B2b);
                v = qb[8+q];    B3a = fma2(v.x, w31p[2*q], B3a); B3b = fma2(v.y, w31p[2*q+1], B3b);
                v = qb[16+q];   B1a = fma2(v.x, w31p[2*q], B1a); B1b = fma2(v.y, w31p[2*q+1], B1b);
            }
            float r23A = bfly(tanh_pre(upadd(add2(A2a, A2b))) * w32) + b32;
            float r23B = bfly(tanh_pre(upadd(add2(B2a, B2b))) * w32) + b32;
            float r4A  = bfly(tanh_pre(upadd(add2(A3a, A3b))) * w32) + b32;
            float r4B  = bfly(tanh_pre(upadd(add2(B3a, B3b))) * w32) + b32;
            float r1nA = bfly(tanh_pre(upadd(add2(A1a, A1b))) * w32) + b32;
            float r1nB = bfly(tanh_pre(upadd(add2(B1a, B1b))) * w32) + b32;

            // ---- k-chains ----------------------------------------------------
            const float cafcA = fmaf(uA, 1.0f/6.0f, 1.0f/6.0f);
            const float cafcB = fmaf(uB, 1.0f/6.0f, 1.0f/6.0f);
            float nA0, nA1, nB0, nB1;
            {
                float k10, k11; kof(Ax0, Ax1, Ar3s1, cafcA, k10, k11);
                float xb0 = fmaf(0.5f, k10, Ax0), xb1 = fmaf(0.5f, k11, Ax1);
                float k20, k21; kof(xb0, xb1, r23A, cafcA, k20, k21);
                float xc0 = fmaf(0.5f, k20, Ax0), xc1 = fmaf(0.5f, k21, Ax1);
                float k30, k31; kof(xc0, xc1, r23A, cafcA, k30, k31);
                float xd0 = Ax0 + k30, xd1 = Ax1 + k31;
                float k40, k41; kof(xd0, xd1, r4A, cafcA, k40, k41);
                nA0 = fmaf(k10 + 2.0f*(k20 + k30) + k40, 1.0f/6.0f, Ax0);
                nA1 = fmaf(k11 + 2.0f*(k21 + k31) + k41, 1.0f/6.0f, Ax1);
            }
            {
                float k10, k11; kof(Bx0, Bx1, Br3s1, cafcB, k10, k11);
                float xb0 = fmaf(0.5f, k10, Bx0), xb1 = fmaf(0.5f, k11, Bx1);
                float k20, k21; kof(xb0, xb1, r23B, cafcB, k20, k21);
                float xc0 = fmaf(0.5f, k20, Bx0), xc1 = fmaf(0.5f, k21, Bx1);
                float k30, k31; kof(xc0, xc1, r23B, cafcB, k30, k31);
                float xd0 = Bx0 + k30, xd1 = Bx1 + k31;
                float k40, k41; kof(xd0, xd1, r4B, cafcB, k40, k41);
                nB0 = fmaf(k10 + 2.0f*(k20 + k30) + k40, 1.0f/6.0f, Bx0);
                nB1 = fmaf(k11 + 2.0f*(k21 + k31) + k41, 1.0f/6.0f, Bx1);
            }

            // ---- next-step S4 partial (ring reads, off-path) -----------------
            ull S4nA = 0ull, S4nB = 0ull;
#pragma unroll
            for (int j = 0; j < 6; ++j) {
                S4nA = fma2(xqA[(p+2+j) & 7], w30p[j], S4nA);
                S4nB = fma2(xqB[(p+2+j) & 7], w30p[j], S4nB);
            }
            S4nA = fma2(pxA, w30p[6], S4nA);
            S4nB = fma2(pxB, w30p[6], S4nB);

            AS4p = S4nA;  BS4p = S4nB;
            AS1s = S4sA;  BS1s = S4sB;
            AUc  = UnA;   BUc  = UnB;
            Ar3s1 = r1nA; Br3s1 = r1nB;
            Ax0 = nA0; Ax1 = nA1;
            Bx0 = nB0; Bx1 = nB1;
        }
    }
}

}  // namespace

extern "C" void kernel_launch(void* const* d_in, const int* in_sizes, int n_in,
                              void* d_out, int out_size) {
    (void)in_sizes; (void)n_in; (void)out_size;
    const float* useq = (const float*)d_in[0];
    const float* xz0  = (const float*)d_in[1];
    const float* r1W0 = (const float*)d_in[2];
    const float* r1b0 = (const float*)d_in[3];
    const float* r1W1 = (const float*)d_in[4];
    const float* r1b1 = (const float*)d_in[5];
    const float* r1W2 = (const float*)d_in[6];
    const float* r1b2 = (const float*)d_in[7];
    const float* r2W0 = (const float*)d_in[8];
    const float* r2b0 = (const float*)d_in[9];
    const float* r2W1 = (const float*)d_in[10];
    const float* r2b1 = (const float*)d_in[11];
    const float* r2W2 = (const float*)d_in[12];
    const float* r2b2 = (const float*)d_in[13];
    const float* r3W0 = (const float*)d_in[14];
    const float* r3b0 = (const float*)d_in[15];
    const float* r3W1 = (const float*)d_in[16];
    const float* r3b1 = (const float*)d_in[17];
    const float* r3W2 = (const float*)d_in[18];
    const float* r3b2 = (const float*)d_in[19];
    float* out = (float*)d_out;

    cudaFuncSetAttribute(rk4_kernel, cudaFuncAttributeMaxDynamicSharedMemorySize,
                         kSmemBytes);

    build_all<<<(2 * kN2 + 127) / 128, 128>>>(
        r1W0, r1b0, r1W1, r1b1, r1W2, r1b2,
        r2W0, r2b0, r2W1, r2b1, r2W2, r2b2);
    rk4_kernel<<<kB / 8, 128, kSmemBytes>>>(useq, xz0,
                                            r3W0, r3b0, r3W1, r3b1, r3W2, r3b2,
                                            out);
}

// round 10
// speedup vs baseline: 1.1570x; 1.1570x over previous
#include <cuda_runtime.h>
#include <math.h>

// ReacPartialGbModel: B=4096 RK4 integrations, T=256 steps.
// R8 structure (best: 1 elem/warp, smem LUTs, r3 software-pipelined) plus:
//  - A-LUT eliminated algebraically (A = 0.1*x0 + 1/6 + (2/3)*R)
//  - layer-1 matvec weights in shared memory (-32 regs, one copy per block)
//  - __launch_bounds__(128,5): 20 warps/SM
// One warp per batch element; lane = hidden unit.

namespace {

constexpr int kT = 256;
constexpr int kB = 4096;
constexpr int kN2 = 1024;              // LUT intervals over [-16,16)
constexpr float kH2    = 1.0f / 32.0f;
constexpr float kInvH2 = 32.0f;
constexpr float kSc    = 2.885390081777927f;  // 2*log2(e)

__device__ __align__(16) float4 g_lutR[kN2];
__device__ __align__(16) float4 g_lutB[kN2];

typedef unsigned long long ull;

// ---------------- helpers ---------------------------------------------------
__device__ __forceinline__ float tanh_acc(float x) {
    float ax = fabsf(x);
    float e  = __expf(-2.0f * ax);
    float r  = __fdividef(1.0f - e, 1.0f + e);
    return copysignf(r, x);
}
__device__ __forceinline__ float tanh_pre(float a) {   // input prescaled 2*log2e
    float e; asm("ex2.approx.f32 %0, %1;" : "=f"(e) : "f"(a));
    float s = e + 1.0f;
    float r; asm("rcp.approx.f32 %0, %1;" : "=f"(r) : "f"(s));
    return fmaf(-2.0f, r, 1.0f);
}
__device__ __forceinline__ ull fma2(ull a, ull b, ull c) {
    ull d; asm("fma.rn.f32x2 %0, %1, %2, %3;" : "=l"(d) : "l"(a), "l"(b), "l"(c));
    return d;
}
__device__ __forceinline__ ull add2(ull a, ull b) {
    ull d; asm("add.rn.f32x2 %0, %1, %2;" : "=l"(d) : "l"(a), "l"(b));
    return d;
}
__device__ __forceinline__ ull pk(float lo, float hi) {
    ull d; asm("mov.b64 %0, {%1, %2};" : "=l"(d) : "f"(lo), "f"(hi));
    return d;
}
__device__ __forceinline__ float upadd(ull v) {
    float lo, hi; asm("mov.b64 {%0, %1}, %2;" : "=f"(lo), "=f"(hi) : "l"(v));
    return lo + hi;
}
__device__ __forceinline__ float bfly(float v) {
#pragma unroll
    for (int m = 16; m > 0; m >>= 1) v += __shfl_xor_sync(0xffffffffu, v, m);
    return v;
}

// ---------------- build kernel ----------------------------------------------
__device__ void eval_raw(float x,
                         const float* __restrict__ w0, const float* __restrict__ b0,
                         const float* __restrict__ w1, const float* __restrict__ b1,
                         const float* __restrict__ w2, const float* __restrict__ b2,
                         float& y_out, float& d_out)
{
    float t0[32], s0[32];
#pragma unroll
    for (int i = 0; i < 32; ++i) {
        float a  = fmaf(w0[i], x, b0[i]);
        float th = tanh_acc(a);
        t0[i] = th;
        s0[i] = (1.0f - th * th) * w0[i];
    }
    float y = b2[0], d = 0.0f;
    for (int j = 0; j < 32; ++j) {
        float a = b1[j], da = 0.0f;
#pragma unroll
        for (int i = 0; i < 32; ++i) {
            float w = w1[i * 32 + j];
            a  = fmaf(t0[i], w, a);
            da = fmaf(s0[i], w, da);
        }
        float th = tanh_acc(a);
        y = fmaf(w2[j], th, y);
        d = fmaf(w2[j] * (1.0f - th * th), da, d);
    }
    y_out = y; d_out = d;
}

__device__ __forceinline__ float4 hermite2(float y0, float d0, float y1, float d1) {
    float hd0 = kH2 * d0, hd1 = kH2 * d1;
    float dy  = y1 - y0;
    return make_float4(y0, hd0,
                       3.0f * dy - 2.0f * hd0 - hd1,
                       -2.0f * dy + hd0 + hd1);
}

__global__ void build_all(const float* __restrict__ W0, const float* __restrict__ B0,
                          const float* __restrict__ W1, const float* __restrict__ B1,
                          const float* __restrict__ W2, const float* __restrict__ B2,
                          const float* __restrict__ V0, const float* __restrict__ C0,
                          const float* __restrict__ V1, const float* __restrict__ C1,
                          const float* __restrict__ V2, const float* __restrict__ C2)
{
    int idx = blockIdx.x * blockDim.x + threadIdx.x;
    if (idx >= 2 * kN2) return;
    int net = idx / kN2;
    int i   = idx - net * kN2;
    float xa = -16.0f + i * kH2;
    float xb = xa + kH2;
    float y0, d0, y1, d1;
    if (net == 0) {
        eval_raw(xa, W0, B0, W1, B1, W2, B2, y0, d0);
        eval_raw(xb, W0, B0, W1, B1, W2, B2, y1, d1);
        // R = r1/0.2 = 1.5*y (r1 = 0.3*y)
        g_lutR[i] = hermite2(1.5f * y0, 1.5f * d0, 1.5f * y1, 1.5f * d1);
    } else {
        eval_raw(xa, V0, C0, V1, C1, V2, C2, y0, d0);
        eval_raw(xb, V0, C0, V1, C1, V2, C2, y1, d1);
        // B = (0.1*Cb + 3*r2)*5, Cb = 0.2x+0.5, r2 = 0.2*y
        float Bv0 = (0.1f * fmaf(0.2f, xa, 0.5f) + 0.6f * y0) * 5.0f;
        float Bv1 = (0.1f * fmaf(0.2f, xb, 0.5f) + 0.6f * y1) * 5.0f;
        float Bd0 = (0.02f + 0.6f * d0) * 5.0f;
        float Bd1 = (0.02f + 0.6f * d1) * 5.0f;
        g_lutB[i] = hermite2(Bv0, Bd0, Bv1, Bd1);
    }
}

// ---------------- main kernel ------------------------------------------------
// smem floats: [bufs 4x224][w31s 256 ull2 = 1024 f][lutR 1024 f4][lutB 1024 f4]
constexpr int kBufFloats = 4 * 224;                    // 896
constexpr int kW31Floats = 256 * 4;                    // 1024 (256 ulonglong2)
constexpr int kSmemBytes = (kBufFloats + kW31Floats) * 4 + 2 * kN2 * 16;  // 40448

__global__ void __launch_bounds__(128, 5)
rk4_kernel(const float* __restrict__ useq, const float* __restrict__ xz0,
           const float* __restrict__ r3W0, const float* __restrict__ r3b0,
           const float* __restrict__ r3W1, const float* __restrict__ r3b1,
           const float* __restrict__ r3W2, const float* __restrict__ r3b2,
           float* __restrict__ out)
{
    extern __shared__ __align__(16) float smemraw[];
    const int wslot = threadIdx.x >> 5;
    const int wid   = blockIdx.x * 4 + wslot;
    const int lane  = threadIdx.x & 31;

    float*      swarp = smemraw + wslot * 224;           // 2x96 parity + 32 qbuf
    ulonglong2* w31s  = reinterpret_cast<ulonglong2*>(smemraw + kBufFloats);
    float4*     sR    = reinterpret_cast<float4*>(smemraw + kBufFloats + kW31Floats);
    float4*     sB    = sR + kN2;

    // ---- stage LUTs + packed layer-1 weights into smem ----------------------
    for (int k = threadIdx.x; k < kN2; k += 128) {
        sR[k] = __ldg(&g_lutR[k]);
        sB[k] = __ldg(&g_lutB[k]);
    }
    for (int idx = threadIdx.x; idx < 256; idx += 128) {
        int q = idx >> 5, l = idx & 31;
        ulonglong2 w;
        w.x = pk(__ldg(&r3W1[(4 * q)     * 32 + l]) * kSc,
                 __ldg(&r3W1[(4 * q + 1) * 32 + l]) * kSc);
        w.y = pk(__ldg(&r3W1[(4 * q + 2) * 32 + l]) * kSc,
                 __ldg(&r3W1[(4 * q + 3) * 32 + l]) * kSc);
        w31s[q * 32 + l] = w;
    }
    __syncthreads();

    // ---- per-lane weights kept in registers ---------------------------------
    ull w30p[8];
    float wu[8];
#pragma unroll
    for (int j = 0; j < 8; ++j)
        w30p[j] = pk(r3W0[(2 * j) * 32 + lane] * kSc,
                     r3W0[(2 * j + 1) * 32 + lane] * kSc);
#pragma unroll
    for (int k = 0; k < 8; ++k) wu[k] = r3W0[(16 + k) * 32 + lane] * kSc;
    const float b30s = r3b0[lane] * kSc;
    const ull   b31p = pk(r3b1[lane] * kSc, 0.0f);
    const float w32  = r3W2[lane], b32 = r3b2[0];

    // ---- state: x scalar, history as packed register ring ------------------
    const float* xz = xz0 + wid * 26;
    float x0 = xz[0], x1 = xz[1];
    ull xq[8];
    float up[8];
#pragma unroll
    for (int j = 0; j < 8; ++j) xq[j] = pk(xz[2 + 2 * j], xz[3 + 2 * j]);
#pragma unroll
    for (int k = 0; k < 8; ++k) up[k] = xz[18 + k];

    const float4* uptr4 = reinterpret_cast<const float4*>(useq + wid * kT);
    float2* outp = reinterpret_cast<float2*>(out) + wid * kT;

    auto kof = [&](float x0v, float x1v, float r3s, float cafc,
                   float& k0, float& k1v) {
        float xf0 = fmaf(x0v, kInvH2, 512.0f);
        float f0  = fminf(fmaxf(floorf(xf0), 0.0f), 1023.0f);
        float t0  = xf0 - f0;
        float4 cR = sR[(int)f0];
        float xf1 = fmaf(x1v, kInvH2, 512.0f);
        float f1  = fminf(fmaxf(floorf(xf1), 0.0f), 1023.0f);
        float t1  = xf1 - f1;
        float4 cB = sB[(int)f1];
        float Rv = fmaf(fmaf(fmaf(cR.w, t0, cR.z), t0, cR.y), t0, cR.x);
        float Bv = fmaf(fmaf(fmaf(cB.w, t1, cB.z), t1, cB.y), t1, cB.x);
        k0  = fmaf(-2.0f / 3.0f, Rv, fmaf(-0.1f, x0v, cafc));
        k1v = (Rv - Bv) + r3s;
    };

    // ---- pipeline bootstrap (step 0, ring phase p=0) ------------------------
    float S1s, Uc, r3s1;
    {
        ull S1 = 0ull;
#pragma unroll
        for (int j = 0; j < 8; ++j) S1 = fma2(xq[j], w30p[j], S1);
        float Ua = b30s, Ub = 0.0f;
#pragma unroll
        for (int k = 0; k < 8; k += 2) {
            Ua = fmaf(up[k],     wu[k],     Ua);
            Ub = fmaf(up[k + 1], wu[k + 1], Ub);
        }
        S1s = upadd(S1);
        Uc  = Ua + Ub;
        swarp[lane] = tanh_pre(S1s + Uc);
        __syncwarp();
        ull C = b31p;
        const ulonglong2* bq = reinterpret_cast<const ulonglong2*>(swarp);
#pragma unroll
        for (int q = 0; q < 8; ++q) {
            ulonglong2 w = w31s[q * 32 + lane];
            ulonglong2 v = bq[q];
            C = fma2(v.x, w.x, C);
            C = fma2(v.y, w.y, C);
        }
        __syncwarp();
        r3s1 = bfly(tanh_pre(upadd(C)) * w32) + b32;
    }
    ull S4p = 0ull;
#pragma unroll
    for (int j = 0; j < 7; ++j) S4p = fma2(xq[(1 + j) & 7], w30p[j], S4p);

#pragma unroll 1
    for (int tb = 0; tb < kT; tb += 8) {
        float4 ua = __ldg(uptr4 + (tb >> 2));
        float4 ub = __ldg(uptr4 + (tb >> 2) + 1);
        float uu[8] = {ua.x, ua.y, ua.z, ua.w, ub.x, ub.y, ub.z, ub.w};

#pragma unroll
        for (int p = 0; p < 8; ++p) {
            const float u = uu[p];
            if (lane == 0) outp[tb + p] = make_float2(x0, x1);
            const float cafc = fmaf(u, 1.0f / 6.0f, 1.0f / 6.0f);

            // ---- fast a3 computation (short path after x arrives) ----------
            ull px = pk(x0, x1);
            float S4s = upadd(fma2(px, w30p[7], S4p));
            float a3_23 = fmaf(0.5f, S1s + S4s, Uc);
            float a3_4  = S4s + Uc;
            float Una = b30s, Unb = 0.0f;
#pragma unroll
            for (int k = 0; k < 6; k += 2) {
                Una = fmaf(up[(p + 1 + k) & 7], wu[k],     Una);
                Unb = fmaf(up[(p + 2 + k) & 7], wu[k + 1], Unb);
            }
            Una = fmaf(up[(p + 7) & 7], wu[6], Una);
            Unb = fmaf(u, wu[7], Unb);
            float Un = Una + Unb;
            float a3_1n = S4s + Un;        // k1-stage preact for step t+1

            // ---- three p3 evals in one broadcast round ----------------------
            float h2  = tanh_pre(a3_23);
            float h3  = tanh_pre(a3_4);
            float h1n = tanh_pre(a3_1n);
            float* buf = swarp + (p & 1) * 96;
            buf[lane]      = h2;
            buf[32 + lane] = h3;
            buf[64 + lane] = h1n;
            __syncwarp();
            ull C2a = b31p, C2b = 0ull, C3a = b31p, C3b = 0ull,
                C1a = b31p, C1b = 0ull;
            const ulonglong2* bq = reinterpret_cast<const ulonglong2*>(buf);
#pragma unroll
            for (int q = 0; q < 8; ++q) {
                ulonglong2 w = w31s[q * 32 + lane];
                ulonglong2 v2 = bq[q];
                C2a = fma2(v2.x, w.x, C2a);
                C2b = fma2(v2.y, w.y, C2b);
                ulonglong2 v3 = bq[8 + q];
                C3a = fma2(v3.x, w.x, C3a);
                C3b = fma2(v3.y, w.y, C3b);
                ulonglong2 v1 = bq[16 + q];
                C1a = fma2(v1.x, w.x, C1a);
                C1b = fma2(v1.y, w.y, C1b);
            }
            // q2 critical -> smem tree; q3, q1n off-path -> butterflies
            float q2 = tanh_pre(upadd(add2(C2a, C2b))) * w32;
            float* qbuf = swarp + 192;
            qbuf[lane] = q2;
            float q3 = tanh_pre(upadd(add2(C3a, C3b))) * w32;
            float q1 = tanh_pre(upadd(add2(C1a, C1b))) * w32;
            __syncwarp();
            ull s0, s1, s2, s3;
            {
                const ulonglong2* qv = reinterpret_cast<const ulonglong2*>(qbuf);
                ulonglong2 a0 = qv[0], a1 = qv[1], a2 = qv[2], a3 = qv[3],
                           a4 = qv[4], a5 = qv[5], a6 = qv[6], a7 = qv[7];
                s0 = add2(add2(a0.x, a0.y), add2(a1.x, a1.y));
                s1 = add2(add2(a2.x, a2.y), add2(a3.x, a3.y));
                s2 = add2(add2(a4.x, a4.y), add2(a5.x, a5.y));
                s3 = add2(add2(a6.x, a6.y), add2(a7.x, a7.y));
            }
            float r3s23 = upadd(add2(add2(s0, s1), add2(s2, s3))) + b32;
            float r3s4  = bfly(q3) + b32;
            float r3s1n = bfly(q1) + b32;

            // ---- RK4 k-chain: stage 1 uses carried r3s1 (starts early) -----
            float k10, k11; kof(x0, x1, r3s1, cafc, k10, k11);
            float xb0 = fmaf(0.5f, k10, x0), xb1 = fmaf(0.5f, k11, x1);
            float k20, k21; kof(xb0, xb1, r3s23, cafc, k20, k21);
            float xc0 = fmaf(0.5f, k20, x0), xc1 = fmaf(0.5f, k21, x1);
            float k30, k31; kof(xc0, xc1, r3s23, cafc, k30, k31);
            float xd0 = x0 + k30, xd1 = x1 + k31;
            float k40, k41; kof(xd0, xd1, r3s4, cafc, k40, k41);

            float nx0 = fmaf(k10 + 2.0f * (k20 + k30) + k40, 1.0f / 6.0f, x0);
            float nx1 = fmaf(k11 + 2.0f * (k21 + k31) + k41, 1.0f / 6.0f, x1);

            // ---- ring + pipeline updates (off critical path) ----------------
            xq[p & 7] = px;
            up[p & 7] = u;
            ull S4n = 0ull;
#pragma unroll
            for (int j = 0; j < 7; ++j)
                S4n = fma2(xq[(p + 2 + j) & 7], w30p[j], S4n);
            S4p = S4n;
            S1s = S4s;
            Uc  = Un;
            r3s1 = r3s1n;
            x0 = nx0; x1 = nx1;
        }
    }
}

}  // namespace

extern "C" void kernel_launch(void* const* d_in, const int* in_sizes, int n_in,
                              void* d_out, int out_size) {
    (void)in_sizes; (void)n_in; (void)out_size;
    const float* useq = (const float*)d_in[0];
    const float* xz0  = (const float*)d_in[1];
    const float* r1W0 = (const float*)d_in[2];
    const float* r1b0 = (const float*)d_in[3];
    const float* r1W1 = (const float*)d_in[4];
    const float* r1b1 = (const float*)d_in[5];
    const float* r1W2 = (const float*)d_in[6];
    const float* r1b2 = (const float*)d_in[7];
    const float* r2W0 = (const float*)d_in[8];
    const float* r2b0 = (const float*)d_in[9];
    const float* r2W1 = (const float*)d_in[10];
    const float* r2b1 = (const float*)d_in[11];
    const float* r2W2 = (const float*)d_in[12];
    const float* r2b2 = (const float*)d_in[13];
    const float* r3W0 = (const float*)d_in[14];
    const float* r3b0 = (const float*)d_in[15];
    const float* r3W1 = (const float*)d_in[16];
    const float* r3b1 = (const float*)d_in[17];
    const float* r3W2 = (const float*)d_in[18];
    const float* r3b2 = (const float*)d_in[19];
    float* out = (float*)d_out;

    cudaFuncSetAttribute(rk4_kernel, cudaFuncAttributeMaxDynamicSharedMemorySize,
                         kSmemBytes);

    build_all<<<(2 * kN2 + 127) / 128, 128>>>(
        r1W0, r1b0, r1W1, r1b1, r1W2, r1b2,
        r2W0, r2b0, r2W1, r2b1, r2W2, r2b2);
    rk4_kernel<<<kB / 4, 128, kSmemBytes>>>(useq, xz0,
                                            r3W0, r3b0, r3W1, r3b1, r3W2, r3b2,
                                            out);
}

// round 11
// speedup vs baseline: 1.1901x; 1.0285x over previous
#include <cuda_runtime.h>
#include <math.h>

// ReacPartialGbModel: B=4096 RK4 integrations, T=256 steps.
// Best-known structure (R8: 1 elem/warp, smem LUTs, r3 software-pipelined) +
//  - A-LUT eliminated algebraically (A = 0.1*x0 + 1/6 + (2/3)*R)
//  - history rings (xq, up) in per-warp smem (off-path reads) -> -24 regs
//  - layer-1 weights w31 kept in REGISTERS (critical matvec chain)
//  - __launch_bounds__(128,5): 20 warps/SM target
// One warp per batch element; lane = hidden unit.

namespace {

constexpr int kT = 256;
constexpr int kB = 4096;
constexpr int kN2 = 1024;              // LUT intervals over [-16,16)
constexpr float kH2    = 1.0f / 32.0f;
constexpr float kInvH2 = 32.0f;
constexpr float kSc    = 2.885390081777927f;  // 2*log2(e)

__device__ __align__(16) float4 g_lutR[kN2];
__device__ __align__(16) float4 g_lutB[kN2];

typedef unsigned long long ull;

// ---------------- helpers ---------------------------------------------------
__device__ __forceinline__ float tanh_acc(float x) {
    float ax = fabsf(x);
    float e  = __expf(-2.0f * ax);
    float r  = __fdividef(1.0f - e, 1.0f + e);
    return copysignf(r, x);
}
__device__ __forceinline__ float tanh_pre(float a) {   // input prescaled 2*log2e
    float e; asm("ex2.approx.f32 %0, %1;" : "=f"(e) : "f"(a));
    float s = e + 1.0f;
    float r; asm("rcp.approx.f32 %0, %1;" : "=f"(r) : "f"(s));
    return fmaf(-2.0f, r, 1.0f);
}
__device__ __forceinline__ ull fma2(ull a, ull b, ull c) {
    ull d; asm("fma.rn.f32x2 %0, %1, %2, %3;" : "=l"(d) : "l"(a), "l"(b), "l"(c));
    return d;
}
__device__ __forceinline__ ull add2(ull a, ull b) {
    ull d; asm("add.rn.f32x2 %0, %1, %2;" : "=l"(d) : "l"(a), "l"(b));
    return d;
}
__device__ __forceinline__ ull pk(float lo, float hi) {
    ull d; asm("mov.b64 %0, {%1, %2};" : "=l"(d) : "f"(lo), "f"(hi));
    return d;
}
__device__ __forceinline__ float upadd(ull v) {
    float lo, hi; asm("mov.b64 {%0, %1}, %2;" : "=f"(lo), "=f"(hi) : "l"(v));
    return lo + hi;
}
__device__ __forceinline__ float bfly(float v) {
#pragma unroll
    for (int m = 16; m > 0; m >>= 1) v += __shfl_xor_sync(0xffffffffu, v, m);
    return v;
}

// ---------------- build kernel ----------------------------------------------
__device__ void eval_raw(float x,
                         const float* __restrict__ w0, const float* __restrict__ b0,
                         const float* __restrict__ w1, const float* __restrict__ b1,
                         const float* __restrict__ w2, const float* __restrict__ b2,
                         float& y_out, float& d_out)
{
    float t0[32], s0[32];
#pragma unroll
    for (int i = 0; i < 32; ++i) {
        float a  = fmaf(w0[i], x, b0[i]);
        float th = tanh_acc(a);
        t0[i] = th;
        s0[i] = (1.0f - th * th) * w0[i];
    }
    float y = b2[0], d = 0.0f;
    for (int j = 0; j < 32; ++j) {
        float a = b1[j], da = 0.0f;
#pragma unroll
        for (int i = 0; i < 32; ++i) {
            float w = w1[i * 32 + j];
            a  = fmaf(t0[i], w, a);
            da = fmaf(s0[i], w, da);
        }
        float th = tanh_acc(a);
        y = fmaf(w2[j], th, y);
        d = fmaf(w2[j] * (1.0f - th * th), da, d);
    }
    y_out = y; d_out = d;
}

__device__ __forceinline__ float4 hermite2(float y0, float d0, float y1, float d1) {
    float hd0 = kH2 * d0, hd1 = kH2 * d1;
    float dy  = y1 - y0;
    return make_float4(y0, hd0,
                       3.0f * dy - 2.0f * hd0 - hd1,
                       -2.0f * dy + hd0 + hd1);
}

__global__ void build_all(const float* __restrict__ W0, const float* __restrict__ B0,
                          const float* __restrict__ W1, const float* __restrict__ B1,
                          const float* __restrict__ W2, const float* __restrict__ B2,
                          const float* __restrict__ V0, const float* __restrict__ C0,
                          const float* __restrict__ V1, const float* __restrict__ C1,
                          const float* __restrict__ V2, const float* __restrict__ C2)
{
    int idx = blockIdx.x * blockDim.x + threadIdx.x;
    if (idx >= 2 * kN2) return;
    int net = idx / kN2;
    int i   = idx - net * kN2;
    float xa = -16.0f + i * kH2;
    float xb = xa + kH2;
    float y0, d0, y1, d1;
    if (net == 0) {
        eval_raw(xa, W0, B0, W1, B1, W2, B2, y0, d0);
        eval_raw(xb, W0, B0, W1, B1, W2, B2, y1, d1);
        // R = r1/0.2 = 1.5*y (r1 = 0.3*y)
        g_lutR[i] = hermite2(1.5f * y0, 1.5f * d0, 1.5f * y1, 1.5f * d1);
    } else {
        eval_raw(xa, V0, C0, V1, C1, V2, C2, y0, d0);
        eval_raw(xb, V0, C0, V1, C1, V2, C2, y1, d1);
        // B = (0.1*Cb + 3*r2)*5, Cb = 0.2x+0.5, r2 = 0.2*y
        float Bv0 = (0.1f * fmaf(0.2f, xa, 0.5f) + 0.6f * y0) * 5.0f;
        float Bv1 = (0.1f * fmaf(0.2f, xb, 0.5f) + 0.6f * y1) * 5.0f;
        float Bd0 = (0.02f + 0.6f * d0) * 5.0f;
        float Bd1 = (0.02f + 0.6f * d1) * 5.0f;
        g_lutB[i] = hermite2(Bv0, Bd0, Bv1, Bd1);
    }
}

// ---------------- main kernel ------------------------------------------------
// smem floats: [bufs 4x224][rings 4x32][lutR 1024 f4][lutB 1024 f4]
constexpr int kBufFloats  = 4 * 224;                  // 896
constexpr int kRingFloats = 4 * 32;                   // 128
constexpr int kSmemBytes  = (kBufFloats + kRingFloats) * 4 + 2 * kN2 * 16;  // 36960

__global__ void __launch_bounds__(128, 5)
rk4_kernel(const float* __restrict__ useq, const float* __restrict__ xz0,
           const float* __restrict__ r3W0, const float* __restrict__ r3b0,
           const float* __restrict__ r3W1, const float* __restrict__ r3b1,
           const float* __restrict__ r3W2, const float* __restrict__ r3b2,
           float* __restrict__ out)
{
    extern __shared__ __align__(16) float smemraw[];
    const int wslot = threadIdx.x >> 5;
    const int wid   = blockIdx.x * 4 + wslot;
    const int lane  = threadIdx.x & 31;

    float* swarp = smemraw + wslot * 224;              // 2x96 parity + 32 qbuf
    float* ring  = smemraw + kBufFloats + wslot * 32;  // xq: 16f (8 ull), up: 8f
    ull*   xqs   = reinterpret_cast<ull*>(ring);
    float* ups   = ring + 16;
    float4* sR = reinterpret_cast<float4*>(smemraw + kBufFloats + kRingFloats);
    float4* sB = sR + kN2;

    // ---- stage LUTs into smem ------------------------------------------------
    for (int k = threadIdx.x; k < kN2; k += 128) {
        sR[k] = __ldg(&g_lutR[k]);
        sB[k] = __ldg(&g_lutB[k]);
    }
    __syncthreads();

    // ---- weights in registers (critical chain) ------------------------------
    ull w30p[8], w31p[16];
    float wu[8];
#pragma unroll
    for (int j = 0; j < 8; ++j)
        w30p[j] = pk(r3W0[(2 * j) * 32 + lane] * kSc,
                     r3W0[(2 * j + 1) * 32 + lane] * kSc);
#pragma unroll
    for (int k = 0; k < 8; ++k) wu[k] = r3W0[(16 + k) * 32 + lane] * kSc;
#pragma unroll
    for (int j = 0; j < 16; ++j)
        w31p[j] = pk(r3W1[(2 * j) * 32 + lane] * kSc,
                     r3W1[(2 * j + 1) * 32 + lane] * kSc);
    const float b30s = r3b0[lane] * kSc;
    const ull   b31p = pk(r3b1[lane] * kSc, 0.0f);
    const float w32  = r3W2[lane], b32 = r3b2[0];

    // ---- state: x in regs, history rings in smem -----------------------------
    const float* xz = xz0 + wid * 26;
    float x0 = xz[0], x1 = xz[1];
    if (lane == 0) {
#pragma unroll
        for (int j = 0; j < 8; ++j) xqs[j] = pk(xz[2 + 2 * j], xz[3 + 2 * j]);
#pragma unroll
        for (int k = 0; k < 8; ++k) ups[k] = xz[18 + k];
    }
    __syncwarp();

    const float4* uptr4 = reinterpret_cast<const float4*>(useq + wid * kT);
    float2* outp = reinterpret_cast<float2*>(out) + wid * kT;

    auto kof = [&](float x0v, float x1v, float r3s, float cafc,
                   float& k0, float& k1v) {
        float xf0 = fmaf(x0v, kInvH2, 512.0f);
        float f0  = fminf(fmaxf(floorf(xf0), 0.0f), 1023.0f);
        float t0  = xf0 - f0;
        float4 cR = sR[(int)f0];
        float xf1 = fmaf(x1v, kInvH2, 512.0f);
        float f1  = fminf(fmaxf(floorf(xf1), 0.0f), 1023.0f);
        float t1  = xf1 - f1;
        float4 cB = sB[(int)f1];
        float Rv = fmaf(fmaf(fmaf(cR.w, t0, cR.z), t0, cR.y), t0, cR.x);
        float Bv = fmaf(fmaf(fmaf(cB.w, t1, cB.z), t1, cB.y), t1, cB.x);
        k0  = fmaf(-2.0f / 3.0f, Rv, fmaf(-0.1f, x0v, cafc));
        k1v = (Rv - Bv) + r3s;
    };

    // ---- pipeline bootstrap (step 0, ring phase p=0) ------------------------
    float S1s, Uc, r3s1;
    {
        ull S1 = 0ull;
#pragma unroll
        for (int j = 0; j < 8; ++j) S1 = fma2(xqs[j], w30p[j], S1);
        float Ua = b30s, Ub = 0.0f;
#pragma unroll
        for (int k = 0; k < 8; k += 2) {
            Ua = fmaf(ups[k],     wu[k],     Ua);
            Ub = fmaf(ups[k + 1], wu[k + 1], Ub);
        }
        S1s = upadd(S1);
        Uc  = Ua + Ub;
        swarp[lane] = tanh_pre(S1s + Uc);
        __syncwarp();
        ull C = b31p;
        const ulonglong2* bq = reinterpret_cast<const ulonglong2*>(swarp);
#pragma unroll
        for (int q = 0; q < 8; ++q) {
            ulonglong2 v = bq[q];
            C = fma2(v.x, w31p[2 * q],     C);
            C = fma2(v.y, w31p[2 * q + 1], C);
        }
        __syncwarp();
        r3s1 = bfly(tanh_pre(upadd(C)) * w32) + b32;
    }
    ull S4p = 0ull;
#pragma unroll
    for (int j = 0; j < 7; ++j) S4p = fma2(xqs[(1 + j) & 7], w30p[j], S4p);

#pragma unroll 1
    for (int tb = 0; tb < kT; tb += 8) {
        float4 ua = __ldg(uptr4 + (tb >> 2));
        float4 ub = __ldg(uptr4 + (tb >> 2) + 1);
        float uu[8] = {ua.x, ua.y, ua.z, ua.w, ub.x, ub.y, ub.z, ub.w};

#pragma unroll
        for (int p = 0; p < 8; ++p) {
            const float u = uu[p];
            const ull px = pk(x0, x1);
            if (lane == 0) {
                outp[tb + p] = make_float2(x0, x1);
                xqs[p & 7] = px;       // slot p not read this step
                ups[p & 7] = u;
            }
            const float cafc = fmaf(u, 1.0f / 6.0f, 1.0f / 6.0f);

            // ---- fast a3 computation (short path after x arrives) ----------
            float S4s = upadd(fma2(px, w30p[7], S4p));
            float a3_23 = fmaf(0.5f, S1s + S4s, Uc);
            float a3_4  = S4s + Uc;
            float Una = b30s, Unb = 0.0f;
#pragma unroll
            for (int k = 0; k < 6; k += 2) {
                Una = fmaf(ups[(p + 1 + k) & 7], wu[k],     Una);
                Unb = fmaf(ups[(p + 2 + k) & 7], wu[k + 1], Unb);
            }
            Una = fmaf(ups[(p + 7) & 7], wu[6], Una);
            Unb = fmaf(u, wu[7], Unb);
            float Un = Una + Unb;
            float a3_1n = S4s + Un;        // k1-stage preact for step t+1

            // ---- three p3 evals in one broadcast round ----------------------
            float h2  = tanh_pre(a3_23);
            float h3  = tanh_pre(a3_4);
            float h1n = tanh_pre(a3_1n);
            float* buf = swarp + (p & 1) * 96;
            buf[lane]      = h2;
            buf[32 + lane] = h3;
            buf[64 + lane] = h1n;
            __syncwarp();
            ull C2a = b31p, C2b = 0ull, C3a = b31p, C3b = 0ull,
                C1a = b31p, C1b = 0ull;
            const ulonglong2* bq = reinterpret_cast<const ulonglong2*>(buf);
#pragma unroll
            for (int q = 0; q < 8; ++q) {
                ulonglong2 v2 = bq[q];
                C2a = fma2(v2.x, w31p[2 * q],     C2a);
                C2b = fma2(v2.y, w31p[2 * q + 1], C2b);
                ulonglong2 v3 = bq[8 + q];
                C3a = fma2(v3.x, w31p[2 * q],     C3a);
                C3b = fma2(v3.y, w31p[2 * q + 1], C3b);
                ulonglong2 v1 = bq[16 + q];
                C1a = fma2(v1.x, w31p[2 * q],     C1a);
                C1b = fma2(v1.y, w31p[2 * q + 1], C1b);
            }
            // q2 critical -> smem tree; q3, q1n off-path -> butterflies
            float q2 = tanh_pre(upadd(add2(C2a, C2b))) * w32;
            float* qbuf = swarp + 192;
            qbuf[lane] = q2;
            float q3 = tanh_pre(upadd(add2(C3a, C3b))) * w32;
            float q1 = tanh_pre(upadd(add2(C1a, C1b))) * w32;
            __syncwarp();
            ull s0, s1, s2, s3;
            {
                const ulonglong2* qv = reinterpret_cast<const ulonglong2*>(qbuf);
                ulonglong2 a0 = qv[0], a1 = qv[1], a2 = qv[2], a3 = qv[3],
                           a4 = qv[4], a5 = qv[5], a6 = qv[6], a7 = qv[7];
                s0 = add2(add2(a0.x, a0.y), add2(a1.x, a1.y));
                s1 = add2(add2(a2.x, a2.y), add2(a3.x, a3.y));
                s2 = add2(add2(a4.x, a4.y), add2(a5.x, a5.y));
                s3 = add2(add2(a6.x, a6.y), add2(a7.x, a7.y));
            }
            float r3s23 = upadd(add2(add2(s0, s1), add2(s2, s3))) + b32;
            float r3s4  = bfly(q3) + b32;
            float r3s1n = bfly(q1) + b32;

            // ---- RK4 k-chain: stage 1 uses carried r3s1 (starts early) -----
            float k10, k11; kof(x0, x1, r3s1, cafc, k10, k11);
            float xb0 = fmaf(0.5f, k10, x0), xb1 = fmaf(0.5f, k11, x1);
            float k20, k21; kof(xb0, xb1, r3s23, cafc, k20, k21);
            float xc0 = fmaf(0.5f, k20, x0), xc1 = fmaf(0.5f, k21, x1);
            float k30, k31; kof(xc0, xc1, r3s23, cafc, k30, k31);
            float xd0 = x0 + k30, xd1 = x1 + k31;
            float k40, k41; kof(xd0, xd1, r3s4, cafc, k40, k41);

            float nx0 = fmaf(k10 + 2.0f * (k20 + k30) + k40, 1.0f / 6.0f, x0);
            float nx1 = fmaf(k11 + 2.0f * (k21 + k31) + k41, 1.0f / 6.0f, x1);

            // ---- next-step S4 partial (smem ring reads, off-path) -----------
            // slots p+2..p+7 with w30p[0..5], plus px (newest) with w30p[6]
            ull S4n = 0ull;
#pragma unroll
            for (int j = 0; j < 6; ++j)
                S4n = fma2(xqs[(p + 2 + j) & 7], w30p[j], S4n);
            S4n = fma2(px, w30p[6], S4n);
            S4p = S4n;
            S1s = S4s;
            Uc  = Un;
            r3s1 = r3s1n;
            x0 = nx0; x1 = nx1;
        }
    }
}

}  // namespace

extern "C" void kernel_launch(void* const* d_in, const int* in_sizes, int n_in,
                              void* d_out, int out_size) {
    (void)in_sizes; (void)n_in; (void)out_size;
    const float* useq = (const float*)d_in[0];
    const float* xz0  = (const float*)d_in[1];
    const float* r1W0 = (const float*)d_in[2];
    const float* r1b0 = (const float*)d_in[3];
    const float* r1W1 = (const float*)d_in[4];
    const float* r1b1 = (const float*)d_in[5];
    const float* r1W2 = (const float*)d_in[6];
    const float* r1b2 = (const float*)d_in[7];
    const float* r2W0 = (const float*)d_in[8];
    const float* r2b0 = (const float*)d_in[9];
    const float* r2W1 = (const float*)d_in[10];
    const float* r2b1 = (const float*)d_in[11];
    const float* r2W2 = (const float*)d_in[12];
    const float* r2b2 = (const float*)d_in[13];
    const float* r3W0 = (const float*)d_in[14];
    const float* r3b0 = (const float*)d_in[15];
    const float* r3W1 = (const float*)d_in[16];
    const float* r3b1 = (const float*)d_in[17];
    const float* r3W2 = (const float*)d_in[18];
    const float* r3b2 = (const float*)d_in[19];
    float* out = (float*)d_out;

    cudaFuncSetAttribute(rk4_kernel, cudaFuncAttributeMaxDynamicSharedMemorySize,
                         kSmemBytes);

    build_all<<<(2 * kN2 + 127) / 128, 128>>>(
        r1W0, r1b0, r1W1, r1b1, r1W2, r1b2,
        r2W0, r2b0, r2W1, r2b1, r2W2, r2b2);
    rk4_kernel<<<kB / 4, 128, kSmemBytes>>>(useq, xz0,
                                            r3W0, r3b0, r3W1, r3b1, r3W2, r3b2,
                                            out);
}

// round 12
// speedup vs baseline: 1.3170x; 1.1067x over previous
#include <cuda_runtime.h>
#include <math.h>

// ReacPartialGbModel: B=4096 RK4 integrations, T=256 steps.
// R8 structure exactly (1 elem/warp, rings+weights in registers, smem LUTs,
// r3 software-pipelined, occ 4) with the A-LUT eliminated algebraically:
//   A(x0) = 0.1*x0 + 1/6 + (2/3)*R(x0)  ->  2 smem tables instead of 3,
//   each kof stage: -1 LDS, -3 FMA cubic, +2 FMA.
// One warp per batch element; lane = hidden unit.

namespace {

constexpr int kT = 256;
constexpr int kB = 4096;
constexpr int kN2 = 1024;              // LUT intervals over [-16,16)
constexpr float kH2    = 1.0f / 32.0f;
constexpr float kInvH2 = 32.0f;
constexpr float kSc    = 2.885390081777927f;  // 2*log2(e)

__device__ __align__(16) float4 g_lutR[kN2];
__device__ __align__(16) float4 g_lutB[kN2];

typedef unsigned long long ull;

// ---------------- helpers ---------------------------------------------------
__device__ __forceinline__ float tanh_acc(float x) {
    float ax = fabsf(x);
    float e  = __expf(-2.0f * ax);
    float r  = __fdividef(1.0f - e, 1.0f + e);
    return copysignf(r, x);
}
__device__ __forceinline__ float tanh_pre(float a) {   // input prescaled 2*log2e
    float e; asm("ex2.approx.f32 %0, %1;" : "=f"(e) : "f"(a));
    float s = e + 1.0f;
    float r; asm("rcp.approx.f32 %0, %1;" : "=f"(r) : "f"(s));
    return fmaf(-2.0f, r, 1.0f);
}
__device__ __forceinline__ ull fma2(ull a, ull b, ull c) {
    ull d; asm("fma.rn.f32x2 %0, %1, %2, %3;" : "=l"(d) : "l"(a), "l"(b), "l"(c));
    return d;
}
__device__ __forceinline__ ull add2(ull a, ull b) {
    ull d; asm("add.rn.f32x2 %0, %1, %2;" : "=l"(d) : "l"(a), "l"(b));
    return d;
}
__device__ __forceinline__ ull pk(float lo, float hi) {
    ull d; asm("mov.b64 %0, {%1, %2};" : "=l"(d) : "f"(lo), "f"(hi));
    return d;
}
__device__ __forceinline__ float upadd(ull v) {
    float lo, hi; asm("mov.b64 {%0, %1}, %2;" : "=f"(lo), "=f"(hi) : "l"(v));
    return lo + hi;
}
__device__ __forceinline__ float bfly(float v) {
#pragma unroll
    for (int m = 16; m > 0; m >>= 1) v += __shfl_xor_sync(0xffffffffu, v, m);
    return v;
}

// ---------------- build kernel ----------------------------------------------
__device__ void eval_raw(float x,
                         const float* __restrict__ w0, const float* __restrict__ b0,
                         const float* __restrict__ w1, const float* __restrict__ b1,
                         const float* __restrict__ w2, const float* __restrict__ b2,
                         float& y_out, float& d_out)
{
    float t0[32], s0[32];
#pragma unroll
    for (int i = 0; i < 32; ++i) {
        float a  = fmaf(w0[i], x, b0[i]);
        float th = tanh_acc(a);
        t0[i] = th;
        s0[i] = (1.0f - th * th) * w0[i];
    }
    float y = b2[0], d = 0.0f;
    for (int j = 0; j < 32; ++j) {
        float a = b1[j], da = 0.0f;
#pragma unroll
        for (int i = 0; i < 32; ++i) {
            float w = w1[i * 32 + j];
            a  = fmaf(t0[i], w, a);
            da = fmaf(s0[i], w, da);
        }
        float th = tanh_acc(a);
        y = fmaf(w2[j], th, y);
        d = fmaf(w2[j] * (1.0f - th * th), da, d);
    }
    y_out = y; d_out = d;
}

__device__ __forceinline__ float4 hermite2(float y0, float d0, float y1, float d1) {
    float hd0 = kH2 * d0, hd1 = kH2 * d1;
    float dy  = y1 - y0;
    return make_float4(y0, hd0,
                       3.0f * dy - 2.0f * hd0 - hd1,
                       -2.0f * dy + hd0 + hd1);
}

__global__ void build_all(const float* __restrict__ W0, const float* __restrict__ B0,
                          const float* __restrict__ W1, const float* __restrict__ B1,
                          const float* __restrict__ W2, const float* __restrict__ B2,
                          const float* __restrict__ V0, const float* __restrict__ C0,
                          const float* __restrict__ V1, const float* __restrict__ C1,
                          const float* __restrict__ V2, const float* __restrict__ C2)
{
    int idx = blockIdx.x * blockDim.x + threadIdx.x;
    if (idx >= 2 * kN2) return;
    int net = idx / kN2;
    int i   = idx - net * kN2;
    float xa = -16.0f + i * kH2;
    float xb = xa + kH2;
    float y0, d0, y1, d1;
    if (net == 0) {
        eval_raw(xa, W0, B0, W1, B1, W2, B2, y0, d0);
        eval_raw(xb, W0, B0, W1, B1, W2, B2, y1, d1);
        // R = r1/0.2 = 1.5*y (r1 = 0.3*y)
        g_lutR[i] = hermite2(1.5f * y0, 1.5f * d0, 1.5f * y1, 1.5f * d1);
    } else {
        eval_raw(xa, V0, C0, V1, C1, V2, C2, y0, d0);
        eval_raw(xb, V0, C0, V1, C1, V2, C2, y1, d1);
        // B = (0.1*Cb + 3*r2)*5, Cb = 0.2x+0.5, r2 = 0.2*y
        float Bv0 = (0.1f * fmaf(0.2f, xa, 0.5f) + 0.6f * y0) * 5.0f;
        float Bv1 = (0.1f * fmaf(0.2f, xb, 0.5f) + 0.6f * y1) * 5.0f;
        float Bd0 = (0.02f + 0.6f * d0) * 5.0f;
        float Bd1 = (0.02f + 0.6f * d1) * 5.0f;
        g_lutB[i] = hermite2(Bv0, Bd0, Bv1, Bd1);
    }
}

// ---------------- main kernel ------------------------------------------------
// smem floats: [bufs 4x224][lutR 1024 f4][lutB 1024 f4]
constexpr int kBufFloats = 4 * 224;                    // 896
constexpr int kSmemBytes = kBufFloats * 4 + 2 * kN2 * 16;  // 36352

__global__ void __launch_bounds__(128, 4)
rk4_kernel(const float* __restrict__ useq, const float* __restrict__ xz0,
           const float* __restrict__ r3W0, const float* __restrict__ r3b0,
           const float* __restrict__ r3W1, const float* __restrict__ r3b1,
           const float* __restrict__ r3W2, const float* __restrict__ r3b2,
           float* __restrict__ out)
{
    extern __shared__ __align__(16) float smemraw[];
    const int wslot = threadIdx.x >> 5;
    const int wid   = blockIdx.x * 4 + wslot;
    const int lane  = threadIdx.x & 31;

    float*  swarp = smemraw + wslot * 224;             // 2x96 parity + 32 qbuf
    float4* sR    = reinterpret_cast<float4*>(smemraw + kBufFloats);
    float4* sB    = sR + kN2;

    // ---- copy LUTs into shared memory --------------------------------------
    for (int k = threadIdx.x; k < kN2; k += 128) {
        sR[k] = __ldg(&g_lutR[k]);
        sB[k] = __ldg(&g_lutB[k]);
    }
    __syncthreads();

    // ---- weights in registers (critical chain), prescaled 2*log2e ----------
    ull w30p[8], w31p[16];
    float wu[8];
#pragma unroll
    for (int j = 0; j < 8; ++j)
        w30p[j] = pk(r3W0[(2 * j) * 32 + lane] * kSc,
                     r3W0[(2 * j + 1) * 32 + lane] * kSc);
#pragma unroll
    for (int k = 0; k < 8; ++k) wu[k] = r3W0[(16 + k) * 32 + lane] * kSc;
#pragma unroll
    for (int j = 0; j < 16; ++j)
        w31p[j] = pk(r3W1[(2 * j) * 32 + lane] * kSc,
                     r3W1[(2 * j + 1) * 32 + lane] * kSc);
    const float b30s = r3b0[lane] * kSc;
    const ull   b31p = pk(r3b1[lane] * kSc, 0.0f);
    const float w32  = r3W2[lane], b32 = r3b2[0];

    // ---- state: x scalar, history as packed register ring ------------------
    const float* xz = xz0 + wid * 26;
    float x0 = xz[0], x1 = xz[1];
    ull xq[8];
    float up[8];
#pragma unroll
    for (int j = 0; j < 8; ++j) xq[j] = pk(xz[2 + 2 * j], xz[3 + 2 * j]);
#pragma unroll
    for (int k = 0; k < 8; ++k) up[k] = xz[18 + k];

    const float4* uptr4 = reinterpret_cast<const float4*>(useq + wid * kT);
    float2* outp = reinterpret_cast<float2*>(out) + wid * kT;

    auto kof = [&](float x0v, float x1v, float r3s, float cafc,
                   float& k0, float& k1v) {
        float xf0 = fmaf(x0v, kInvH2, 512.0f);
        float f0  = fminf(fmaxf(floorf(xf0), 0.0f), 1023.0f);
        float t0  = xf0 - f0;
        float4 cR = sR[(int)f0];
        float xf1 = fmaf(x1v, kInvH2, 512.0f);
        float f1  = fminf(fmaxf(floorf(xf1), 0.0f), 1023.0f);
        float t1  = xf1 - f1;
        float4 cB = sB[(int)f1];
        float Rv = fmaf(fmaf(fmaf(cR.w, t0, cR.z), t0, cR.y), t0, cR.x);
        float Bv = fmaf(fmaf(fmaf(cB.w, t1, cB.z), t1, cB.y), t1, cB.x);
        k0  = fmaf(-2.0f / 3.0f, Rv, fmaf(-0.1f, x0v, cafc));
        k1v = (Rv - Bv) + r3s;
    };

    // ---- pipeline bootstrap (step 0, ring phase p=0) ------------------------
    float S1s, Uc, r3s1;
    {
        ull S1 = 0ull;
#pragma unroll
        for (int j = 0; j < 8; ++j) S1 = fma2(xq[j], w30p[j], S1);
        float Ua = b30s, Ub = 0.0f;
#pragma unroll
        for (int k = 0; k < 8; k += 2) {
            Ua = fmaf(up[k],     wu[k],     Ua);
            Ub = fmaf(up[k + 1], wu[k + 1], Ub);
        }
        S1s = upadd(S1);
        Uc  = Ua + Ub;
        swarp[lane] = tanh_pre(S1s + Uc);
        __syncwarp();
        ull C = b31p;
        const ulonglong2* bq = reinterpret_cast<const ulonglong2*>(swarp);
#pragma unroll
        for (int q = 0; q < 8; ++q) {
            ulonglong2 v = bq[q];
            C = fma2(v.x, w31p[2 * q],     C);
            C = fma2(v.y, w31p[2 * q + 1], C);
        }
        __syncwarp();
        r3s1 = bfly(tanh_pre(upadd(C)) * w32) + b32;
    }
    ull S4p = 0ull;
#pragma unroll
    for (int j = 0; j < 7; ++j) S4p = fma2(xq[(1 + j) & 7], w30p[j], S4p);

#pragma unroll 1
    for (int tb = 0; tb < kT; tb += 8) {
        float4 ua = __ldg(uptr4 + (tb >> 2));
        float4 ub = __ldg(uptr4 + (tb >> 2) + 1);
        float uu[8] = {ua.x, ua.y, ua.z, ua.w, ub.x, ub.y, ub.z, ub.w};

#pragma unroll
        for (int p = 0; p < 8; ++p) {
            const float u = uu[p];
            if (lane == 0) outp[tb + p] = make_float2(x0, x1);
            const float cafc = fmaf(u, 1.0f / 6.0f, 1.0f / 6.0f);

            // ---- fast a3 computation (short path after x arrives) ----------
            ull px = pk(x0, x1);
            float S4s = upadd(fma2(px, w30p[7], S4p));
            float a3_23 = fmaf(0.5f, S1s + S4s, Uc);
            float a3_4  = S4s + Uc;
            float Una = b30s, Unb = 0.0f;
#pragma unroll
            for (int k = 0; k < 6; k += 2) {
                Una = fmaf(up[(p + 1 + k) & 7], wu[k],     Una);
                Unb = fmaf(up[(p + 2 + k) & 7], wu[k + 1], Unb);
            }
            Una = fmaf(up[(p + 7) & 7], wu[6], Una);
            Unb = fmaf(u, wu[7], Unb);
            float Un = Una + Unb;
            float a3_1n = S4s + Un;        // k1-stage preact for step t+1

            // ---- three p3 evals in one broadcast round ----------------------
            float h2  = tanh_pre(a3_23);
            float h3  = tanh_pre(a3_4);
            float h1n = tanh_pre(a3_1n);
            float* buf = swarp + (p & 1) * 96;
            buf[lane]      = h2;
            buf[32 + lane] = h3;
            buf[64 + lane] = h1n;
            __syncwarp();
            ull C2a = b31p, C2b = 0ull, C3a = b31p, C3b = 0ull,
                C1a = b31p, C1b = 0ull;
            const ulonglong2* bq = reinterpret_cast<const ulonglong2*>(buf);
#pragma unroll
            for (int q = 0; q < 8; ++q) {
                ulonglong2 v2 = bq[q];
                C2a = fma2(v2.x, w31p[2 * q],     C2a);
                C2b = fma2(v2.y, w31p[2 * q + 1], C2b);
                ulonglong2 v3 = bq[8 + q];
                C3a = fma2(v3.x, w31p[2 * q],     C3a);
                C3b = fma2(v3.y, w31p[2 * q + 1], C3b);
                ulonglong2 v1 = bq[16 + q];
                C1a = fma2(v1.x, w31p[2 * q],     C1a);
                C1b = fma2(v1.y, w31p[2 * q + 1], C1b);
            }
            // q2 critical -> smem tree; q3, q1n off-path -> butterflies
            float q2 = tanh_pre(upadd(add2(C2a, C2b))) * w32;
            float* qbuf = swarp + 192;
            qbuf[lane] = q2;
            float q3 = tanh_pre(upadd(add2(C3a, C3b))) * w32;
            float q1 = tanh_pre(upadd(add2(C1a, C1b))) * w32;
            __syncwarp();
            ull s0, s1, s2, s3;
            {
                const ulonglong2* qv = reinterpret_cast<const ulonglong2*>(qbuf);
                ulonglong2 a0 = qv[0], a1 = qv[1], a2 = qv[2], a3 = qv[3],
                           a4 = qv[4], a5 = qv[5], a6 = qv[6], a7 = qv[7];
                s0 = add2(add2(a0.x, a0.y), add2(a1.x, a1.y));
                s1 = add2(add2(a2.x, a2.y), add2(a3.x, a3.y));
                s2 = add2(add2(a4.x, a4.y), add2(a5.x, a5.y));
                s3 = add2(add2(a6.x, a6.y), add2(a7.x, a7.y));
            }
            float r3s23 = upadd(add2(add2(s0, s1), add2(s2, s3))) + b32;
            float r3s4  = bfly(q3) + b32;
            float r3s1n = bfly(q1) + b32;

            // ---- RK4 k-chain: stage 1 uses carried r3s1 (starts early) -----
            float k10, k11; kof(x0, x1, r3s1, cafc, k10, k11);
            float xb0 = fmaf(0.5f, k10, x0), xb1 = fmaf(0.5f, k11, x1);
            float k20, k21; kof(xb0, xb1, r3s23, cafc, k20, k21);
            float xc0 = fmaf(0.5f, k20, x0), xc1 = fmaf(0.5f, k21, x1);
            float k30, k31; kof(xc0, xc1, r3s23, cafc, k30, k31);
            float xd0 = x0 + k30, xd1 = x1 + k31;
            float k40, k41; kof(xd0, xd1, r3s4, cafc, k40, k41);

            float nx0 = fmaf(k10 + 2.0f * (k20 + k30) + k40, 1.0f / 6.0f, x0);
            float nx1 = fmaf(k11 + 2.0f * (k21 + k31) + k41, 1.0f / 6.0f, x1);

            // ---- ring + pipeline updates (off critical path) ----------------
            xq[p & 7] = px;
            up[p & 7] = u;
            ull S4n = 0ull;
#pragma unroll
            for (int j = 0; j < 7; ++j)
                S4n = fma2(xq[(p + 2 + j) & 7], w30p[j], S4n);
            S4p = S4n;
            S1s = S4s;
            Uc  = Un;
            r3s1 = r3s1n;
            x0 = nx0; x1 = nx1;
        }
    }
}

}  // namespace

extern "C" void kernel_launch(void* const* d_in, const int* in_sizes, int n_in,
                              void* d_out, int out_size) {
    (void)in_sizes; (void)n_in; (void)out_size;
    const float* useq = (const float*)d_in[0];
    const float* xz0  = (const float*)d_in[1];
    const float* r1W0 = (const float*)d_in[2];
    const float* r1b0 = (const float*)d_in[3];
    const float* r1W1 = (const float*)d_in[4];
    const float* r1b1 = (const float*)d_in[5];
    const float* r1W2 = (const float*)d_in[6];
    const float* r1b2 = (const float*)d_in[7];
    const float* r2W0 = (const float*)d_in[8];
    const float* r2b0 = (const float*)d_in[9];
    const float* r2W1 = (const float*)d_in[10];
    const float* r2b1 = (const float*)d_in[11];
    const float* r2W2 = (const float*)d_in[12];
    const float* r2b2 = (const float*)d_in[13];
    const float* r3W0 = (const float*)d_in[14];
    const float* r3b0 = (const float*)d_in[15];
    const float* r3W1 = (const float*)d_in[16];
    const float* r3b1 = (const float*)d_in[17];
    const float* r3W2 = (const float*)d_in[18];
    const float* r3b2 = (const float*)d_in[19];
    float* out = (float*)d_out;

    cudaFuncSetAttribute(rk4_kernel, cudaFuncAttributeMaxDynamicSharedMemorySize,
                         kSmemBytes);

    build_all<<<(2 * kN2 + 127) / 128, 128>>>(
        r1W0, r1b0, r1W1, r1b1, r1W2, r1b2,
        r2W0, r2b0, r2W1, r2b1, r2W2, r2b2);
    rk4_kernel<<<kB / 4, 128, kSmemBytes>>>(useq, xz0,
                                            r3W0, r3b0, r3W1, r3b1, r3W2, r3b2,
                                            out);
}